// round 1
// baseline (speedup 1.0000x reference)
#include <cuda_runtime.h>
#include <math.h>

#define BB   2
#define LL   4096
#define DD   1024
#define NH   16
#define HDIM 64
#define BSZ  256
#define NBLK (LL / BSZ)     // 16
#define MR   (BB * LL)      // 8192

// Scratch (allocation-free, __device__ globals)
__device__ float g_Q[BB * NH * LL * HDIM];
__device__ float g_K[BB * NH * LL * HDIM];
__device__ float g_V[BB * NH * LL * HDIM];
__device__ float g_O[MR * DD];

// ---------------------------------------------------------------------------
// SGEMM: C[M,N] = A[M,K] * B[N,K]^T    (both operands K-major, row-major)
// 128x128 tile, BK=16, 256 threads, 8x8 micro-tile per thread.
// MODE 0: epilogue scatters into g_Q/g_K/g_V ([B,H,L,HD] layout), N=3072
// MODE 1: plain row-major write to C
// ---------------------------------------------------------------------------
template <int MODE>
__global__ __launch_bounds__(256)
void sgemm_bt(const float* __restrict__ A, const float* __restrict__ Bm,
              float* __restrict__ C, int Kdim, int Ndim)
{
    __shared__ float As[16][128];
    __shared__ float Bs[16][128];

    const int m0 = blockIdx.y * 128;
    const int n0 = blockIdx.x * 128;
    const int t  = threadIdx.x;
    const int tr = t >> 4;   // 0..15
    const int tc = t & 15;   // 0..15

    float acc[8][8];
#pragma unroll
    for (int i = 0; i < 8; i++)
#pragma unroll
        for (int j = 0; j < 8; j++) acc[i][j] = 0.f;

    for (int k0 = 0; k0 < Kdim; k0 += 16) {
        // Load A tile and B tile (each 128 rows x 16 k), store transposed [k][row]
#pragma unroll
        for (int u = 0; u < 2; u++) {
            int idx = t + u * 256;          // 0..511
            int row = idx >> 2;             // 0..127
            int kq  = (idx & 3) << 2;       // 0,4,8,12
            float4 va = *(const float4*)(A + (size_t)(m0 + row) * Kdim + k0 + kq);
            As[kq + 0][row] = va.x; As[kq + 1][row] = va.y;
            As[kq + 2][row] = va.z; As[kq + 3][row] = va.w;
            float4 vb = *(const float4*)(Bm + (size_t)(n0 + row) * Kdim + k0 + kq);
            Bs[kq + 0][row] = vb.x; Bs[kq + 1][row] = vb.y;
            Bs[kq + 2][row] = vb.z; Bs[kq + 3][row] = vb.w;
        }
        __syncthreads();

#pragma unroll
        for (int kk = 0; kk < 16; kk++) {
            float ar[8], br[8];
            *(float4*)(ar)     = *(const float4*)&As[kk][tr * 8];
            *(float4*)(ar + 4) = *(const float4*)&As[kk][tr * 8 + 4];
            *(float4*)(br)     = *(const float4*)&Bs[kk][tc * 8];
            *(float4*)(br + 4) = *(const float4*)&Bs[kk][tc * 8 + 4];
#pragma unroll
            for (int i = 0; i < 8; i++)
#pragma unroll
                for (int j = 0; j < 8; j++)
                    acc[i][j] += ar[i] * br[j];
        }
        __syncthreads();
    }

    if (MODE == 1) {
#pragma unroll
        for (int i = 0; i < 8; i++) {
            int m = m0 + tr * 8 + i;
#pragma unroll
            for (int j = 0; j < 8; j += 4) {
                int n = n0 + tc * 8 + j;
                float4 v = make_float4(acc[i][j], acc[i][j+1], acc[i][j+2], acc[i][j+3]);
                *(float4*)(C + (size_t)m * Ndim + n) = v;
            }
        }
    } else {
        // n = sel*1024 + h*64 + hd  ;  m = b*4096 + l
#pragma unroll
        for (int i = 0; i < 8; i++) {
            int m = m0 + tr * 8 + i;
            int b = m >> 12;
            int l = m & (LL - 1);
#pragma unroll
            for (int j = 0; j < 8; j += 4) {
                int n   = n0 + tc * 8 + j;
                int sel = n >> 10;
                int h   = (n >> 6) & (NH - 1);
                int hd  = n & (HDIM - 1);
                float* dst = (sel == 0) ? g_Q : (sel == 1) ? g_K : g_V;
                float4 v = make_float4(acc[i][j], acc[i][j+1], acc[i][j+2], acc[i][j+3]);
                *(float4*)(dst + ((size_t)(b * NH + h) * LL + l) * HDIM + hd) = v;
            }
        }
    }
}

// ---------------------------------------------------------------------------
// RoPE (in-place on g_Q and g_K). One warp per 64-float row; lane i owns
// pair (x[2i], x[2i+1]) -> writes out[i], out[32+i]. Reads before writes,
// separated by __syncwarp().
// ---------------------------------------------------------------------------
__global__ void rope_kernel()
{
    const int nrows = BB * NH * LL;
    int gw   = (blockIdx.x * blockDim.x + threadIdx.x) >> 5;
    int lane = threadIdx.x & 31;

    float* buf = (gw < nrows) ? g_Q : g_K;
    int row = (gw < nrows) ? gw : gw - nrows;
    int l   = row & (LL - 1);

    float* p = buf + (size_t)row * HDIM;
    float2 xv = *(const float2*)(p + 2 * lane);

    // inv_freq = 10000^(-lane/32)
    float freq = expf(-(float)lane * (9.210340371976184f / 32.0f));
    float tt = (float)l * freq;
    float c = cosf(tt), s = sinf(tt);

    float o1 = xv.x * c - xv.y * s;
    float o2 = xv.y * c + xv.x * s;
    __syncwarp();
    p[lane]      = o1;
    p[lane + 32] = o2;
}

// ---------------------------------------------------------------------------
// Block-local causal attention. One CTA per (b, h, block). K/V tiles
// (256x64 fp32 each = 128 KB) in dynamic shared memory. One thread per
// query row; q and acc in registers; online softmax (rescale only on new
// max, which is rare). Warp-uniform causal bound skips ~45% of work.
// Output written directly in [B, L, D] layout for the final GEMM.
// ---------------------------------------------------------------------------
__global__ __launch_bounds__(256, 1)
void attn_kernel()
{
    extern __shared__ float sm[];
    float4* Ks4 = (float4*)sm;
    float4* Vs4 = (float4*)(sm + BSZ * HDIM);

    int cta = blockIdx.x;
    int nb  = cta & (NBLK - 1);
    int bh  = cta >> 4;                 // b*NH + h
    int rowbase = bh * LL + nb * BSZ;

    const float4* Kg = (const float4*)(g_K + (size_t)rowbase * HDIM);
    const float4* Vg = (const float4*)(g_V + (size_t)rowbase * HDIM);
    for (int idx = threadIdx.x; idx < BSZ * HDIM / 4; idx += 256) {
        Ks4[idx] = Kg[idx];
        Vs4[idx] = Vg[idx];
    }

    const int i = threadIdx.x;          // query row in block
    float q[64];
    const float4* Qg = (const float4*)(g_Q + (size_t)(rowbase + i) * HDIM);
#pragma unroll
    for (int d = 0; d < 16; d++) ((float4*)q)[d] = Qg[d];
    __syncthreads();

    float mmax = -1e30f, lsum = 0.f;
    float acc[64];
#pragma unroll
    for (int d = 0; d < 64; d++) acc[d] = 0.f;

    const int jmax = i | 31;            // warp-uniform causal bound
    for (int j = 0; j <= jmax; j++) {
        float s = 0.f;
#pragma unroll
        for (int d = 0; d < 16; d++) {
            float4 k4 = Ks4[j * 16 + d];
            s += q[4*d+0] * k4.x + q[4*d+1] * k4.y
               + q[4*d+2] * k4.z + q[4*d+3] * k4.w;
        }
        s *= 0.125f;                    // HD^-0.5
        if (j <= i) {
            if (s <= mmax) {
                float p = __expf(s - mmax);
                lsum += p;
#pragma unroll
                for (int d = 0; d < 16; d++) {
                    float4 v4 = Vs4[j * 16 + d];
                    acc[4*d+0] += p * v4.x;
                    acc[4*d+1] += p * v4.y;
                    acc[4*d+2] += p * v4.z;
                    acc[4*d+3] += p * v4.w;
                }
            } else {                    // new max: rescale (rare)
                float cc = __expf(mmax - s);
                mmax = s;
                lsum = lsum * cc + 1.f;
#pragma unroll
                for (int d = 0; d < 16; d++) {
                    float4 v4 = Vs4[j * 16 + d];
                    acc[4*d+0] = acc[4*d+0] * cc + v4.x;
                    acc[4*d+1] = acc[4*d+1] * cc + v4.y;
                    acc[4*d+2] = acc[4*d+2] * cc + v4.z;
                    acc[4*d+3] = acc[4*d+3] * cc + v4.w;
                }
            }
        }
    }

    float inv = 1.f / lsum;
    int b = bh >> 4;                    // NH = 16
    int h = bh & (NH - 1);
    float* Og = g_O + (size_t)(b * LL + nb * BSZ + i) * DD + h * HDIM;
#pragma unroll
    for (int d = 0; d < 16; d++) {
        float4 o = make_float4(acc[4*d+0] * inv, acc[4*d+1] * inv,
                               acc[4*d+2] * inv, acc[4*d+3] * inv);
        ((float4*)Og)[d] = o;
    }
}

// ---------------------------------------------------------------------------
extern "C" void kernel_launch(void* const* d_in, const int* in_sizes, int n_in,
                              void* d_out, int out_size)
{
    const float* x    = (const float*)d_in[0];
    const float* Wqkv = (const float*)d_in[1];
    const float* Wout = (const float*)d_in[2];
    float* out = (float*)d_out;

    void* Oaddr = nullptr;
    cudaGetSymbolAddress(&Oaddr, g_O);

    cudaFuncSetAttribute(attn_kernel, cudaFuncAttributeMaxDynamicSharedMemorySize,
                         2 * BSZ * HDIM * (int)sizeof(float));

    // 1) QKV projection, scattered into [B,H,L,HD] Q/K/V
    sgemm_bt<0><<<dim3(3 * DD / 128, MR / 128), 256>>>(x, Wqkv, nullptr, DD, 3 * DD);

    // 2) RoPE on Q and K (in place)
    rope_kernel<<<(2 * BB * NH * LL) / 8, 256>>>();

    // 3) Block-local causal attention -> g_O in [B,L,D] layout
    attn_kernel<<<BB * NH * NBLK, 256, 2 * BSZ * HDIM * (int)sizeof(float)>>>();

    // 4) Output projection
    sgemm_bt<1><<<dim3(DD / 128, MR / 128), 256>>>((const float*)Oaddr, Wout, out, DD, DD);
}

// round 2
// speedup vs baseline: 2.3189x; 2.3189x over previous
#include <cuda_runtime.h>
#include <math.h>

#define BB   2
#define LL   4096
#define DD   1024
#define NH   16
#define HDIM 64
#define BSZ  256
#define NBLK (LL / BSZ)     // 16
#define MR   (BB * LL)      // 8192

// Scratch (allocation-free, __device__ globals)
__device__ float g_Q[BB * NH * LL * HDIM];
__device__ float g_K[BB * NH * LL * HDIM];
__device__ float g_V[BB * NH * LL * HDIM];
__device__ float g_O[MR * DD];

__device__ __forceinline__ float f2tf32(float x) {
    asm("cvt.rna.tf32.f32 %0, %0;" : "+f"(x));
    return x;
}

__device__ __forceinline__ void mma_tf32(float* d, const unsigned* a, const unsigned* b) {
    asm volatile(
        "mma.sync.aligned.m16n8k8.row.col.f32.tf32.tf32.f32 "
        "{%0,%1,%2,%3}, {%4,%5,%6,%7}, {%8,%9}, {%0,%1,%2,%3};\n"
        : "+f"(d[0]), "+f"(d[1]), "+f"(d[2]), "+f"(d[3])
        : "r"(a[0]), "r"(a[1]), "r"(a[2]), "r"(a[3]),
          "r"(b[0]), "r"(b[1]));
}

// ---------------------------------------------------------------------------
// tf32 tensor-core GEMM: C[M,N] = A[M,K] * B[N,K]^T  (both K-major row-major)
// 128x128 CTA tile, BK=32, 256 threads = 8 warps (2x4), warp tile 64x32,
// mma.sync m16n8k8 tf32. SMEM [row][k] stride 36 -> conflict-free STS.128
// fill and conflict-free fragment LDS.
// MODE 0: epilogue scatters into g_Q/g_K/g_V ([B,H,L,HD] layout)
// MODE 1: plain row-major write to C
// ---------------------------------------------------------------------------
template <int MODE>
__global__ __launch_bounds__(256)
void mm_tf32(const float* __restrict__ A, const float* __restrict__ Bm,
             float* __restrict__ C, int Kdim, int Ndim)
{
    __shared__ float As[128][36];
    __shared__ float Bs[128][36];

    const int m0 = blockIdx.y * 128;
    const int n0 = blockIdx.x * 128;
    const int t  = threadIdx.x;
    const int warp = t >> 5, lane = t & 31;
    const int wm = (warp >> 2) * 64;   // warpM in {0,64}
    const int wn = (warp & 3) * 32;    // warpN in {0,32,64,96}
    const int g = lane >> 2;           // 0..7
    const int q = lane & 3;            // 0..3

    float acc[4][4][4];
#pragma unroll
    for (int i = 0; i < 4; i++)
#pragma unroll
        for (int j = 0; j < 4; j++)
#pragma unroll
            for (int r = 0; r < 4; r++) acc[i][j][r] = 0.f;

    for (int k0 = 0; k0 < Kdim; k0 += 32) {
#pragma unroll
        for (int u = 0; u < 4; u++) {
            int idx = t + u * 256;          // 0..1023
            int row = idx >> 3;             // 0..127
            int kc  = (idx & 7) << 2;       // 0,4,...,28
            float4 va = *(const float4*)(A + (size_t)(m0 + row) * Kdim + k0 + kc);
            *(float4*)&As[row][kc] =
                make_float4(f2tf32(va.x), f2tf32(va.y), f2tf32(va.z), f2tf32(va.w));
            float4 vb = *(const float4*)(Bm + (size_t)(n0 + row) * Kdim + k0 + kc);
            *(float4*)&Bs[row][kc] =
                make_float4(f2tf32(vb.x), f2tf32(vb.y), f2tf32(vb.z), f2tf32(vb.w));
        }
        __syncthreads();

#pragma unroll
        for (int kk = 0; kk < 4; kk++) {
            const int k8 = kk * 8;
            unsigned af[4][4], bf[4][2];
#pragma unroll
            for (int mi = 0; mi < 4; mi++) {
                int m = wm + mi * 16 + g;
                af[mi][0] = __float_as_uint(As[m][k8 + q]);
                af[mi][1] = __float_as_uint(As[m + 8][k8 + q]);
                af[mi][2] = __float_as_uint(As[m][k8 + q + 4]);
                af[mi][3] = __float_as_uint(As[m + 8][k8 + q + 4]);
            }
#pragma unroll
            for (int ni = 0; ni < 4; ni++) {
                int n = wn + ni * 8 + g;
                bf[ni][0] = __float_as_uint(Bs[n][k8 + q]);
                bf[ni][1] = __float_as_uint(Bs[n][k8 + q + 4]);
            }
#pragma unroll
            for (int mi = 0; mi < 4; mi++)
#pragma unroll
                for (int ni = 0; ni < 4; ni++)
                    mma_tf32(acc[mi][ni], af[mi], bf[ni]);
        }
        __syncthreads();
    }

    // Epilogue. c0,c1 -> (row, 2q),(row, 2q+1); c2,c3 -> (row+8, ...)
#pragma unroll
    for (int mi = 0; mi < 4; mi++) {
        int mA = m0 + wm + mi * 16 + g;
#pragma unroll
        for (int ni = 0; ni < 4; ni++) {
            int n = n0 + wn + ni * 8 + 2 * q;
            float2 v0 = make_float2(acc[mi][ni][0], acc[mi][ni][1]);
            float2 v1 = make_float2(acc[mi][ni][2], acc[mi][ni][3]);
            if (MODE == 1) {
                *(float2*)(C + (size_t)mA * Ndim + n) = v0;
                *(float2*)(C + (size_t)(mA + 8) * Ndim + n) = v1;
            } else {
                int sel = n >> 10;
                int h   = (n >> 6) & (NH - 1);
                int hd  = n & (HDIM - 1);
                float* dst = (sel == 0) ? g_Q : (sel == 1) ? g_K : g_V;
                int b0r = mA >> 12, l0 = mA & (LL - 1);
                int b1r = (mA + 8) >> 12, l1 = (mA + 8) & (LL - 1);
                *(float2*)(dst + ((size_t)(b0r * NH + h) * LL + l0) * HDIM + hd) = v0;
                *(float2*)(dst + ((size_t)(b1r * NH + h) * LL + l1) * HDIM + hd) = v1;
            }
        }
    }
}

// ---------------------------------------------------------------------------
// RoPE (in-place on g_Q and g_K). One warp per 64-float row.
// ---------------------------------------------------------------------------
__global__ void rope_kernel()
{
    const int nrows = BB * NH * LL;
    int gw   = (blockIdx.x * blockDim.x + threadIdx.x) >> 5;
    int lane = threadIdx.x & 31;

    float* buf = (gw < nrows) ? g_Q : g_K;
    int row = (gw < nrows) ? gw : gw - nrows;
    int l   = row & (LL - 1);

    float* p = buf + (size_t)row * HDIM;
    float2 xv = *(const float2*)(p + 2 * lane);

    float freq = expf(-(float)lane * (9.210340371976184f / 32.0f));
    float tt = (float)l * freq;
    float c = cosf(tt), s = sinf(tt);

    float o1 = xv.x * c - xv.y * s;
    float o2 = xv.y * c + xv.x * s;
    __syncwarp();
    p[lane]      = o1;
    p[lane + 32] = o2;
}

// ---------------------------------------------------------------------------
// Block-local causal attention (unchanged from round 1).
// ---------------------------------------------------------------------------
__global__ __launch_bounds__(256, 1)
void attn_kernel()
{
    extern __shared__ float sm[];
    float4* Ks4 = (float4*)sm;
    float4* Vs4 = (float4*)(sm + BSZ * HDIM);

    int cta = blockIdx.x;
    int nb  = cta & (NBLK - 1);
    int bh  = cta >> 4;
    int rowbase = bh * LL + nb * BSZ;

    const float4* Kg = (const float4*)(g_K + (size_t)rowbase * HDIM);
    const float4* Vg = (const float4*)(g_V + (size_t)rowbase * HDIM);
    for (int idx = threadIdx.x; idx < BSZ * HDIM / 4; idx += 256) {
        Ks4[idx] = Kg[idx];
        Vs4[idx] = Vg[idx];
    }

    const int i = threadIdx.x;
    float q[64];
    const float4* Qg = (const float4*)(g_Q + (size_t)(rowbase + i) * HDIM);
#pragma unroll
    for (int d = 0; d < 16; d++) ((float4*)q)[d] = Qg[d];
    __syncthreads();

    float mmax = -1e30f, lsum = 0.f;
    float acc[64];
#pragma unroll
    for (int d = 0; d < 64; d++) acc[d] = 0.f;

    const int jmax = i | 31;
    for (int j = 0; j <= jmax; j++) {
        float s = 0.f;
#pragma unroll
        for (int d = 0; d < 16; d++) {
            float4 k4 = Ks4[j * 16 + d];
            s += q[4*d+0] * k4.x + q[4*d+1] * k4.y
               + q[4*d+2] * k4.z + q[4*d+3] * k4.w;
        }
        s *= 0.125f;
        if (j <= i) {
            if (s <= mmax) {
                float p = __expf(s - mmax);
                lsum += p;
#pragma unroll
                for (int d = 0; d < 16; d++) {
                    float4 v4 = Vs4[j * 16 + d];
                    acc[4*d+0] += p * v4.x;
                    acc[4*d+1] += p * v4.y;
                    acc[4*d+2] += p * v4.z;
                    acc[4*d+3] += p * v4.w;
                }
            } else {
                float cc = __expf(mmax - s);
                mmax = s;
                lsum = lsum * cc + 1.f;
#pragma unroll
                for (int d = 0; d < 16; d++) {
                    float4 v4 = Vs4[j * 16 + d];
                    acc[4*d+0] = acc[4*d+0] * cc + v4.x;
                    acc[4*d+1] = acc[4*d+1] * cc + v4.y;
                    acc[4*d+2] = acc[4*d+2] * cc + v4.z;
                    acc[4*d+3] = acc[4*d+3] * cc + v4.w;
                }
            }
        }
    }

    float inv = 1.f / lsum;
    int b = bh >> 4;
    int h = bh & (NH - 1);
    float* Og = g_O + (size_t)(b * LL + nb * BSZ + i) * DD + h * HDIM;
#pragma unroll
    for (int d = 0; d < 16; d++) {
        float4 o = make_float4(acc[4*d+0] * inv, acc[4*d+1] * inv,
                               acc[4*d+2] * inv, acc[4*d+3] * inv);
        ((float4*)Og)[d] = o;
    }
}

// ---------------------------------------------------------------------------
extern "C" void kernel_launch(void* const* d_in, const int* in_sizes, int n_in,
                              void* d_out, int out_size)
{
    const float* x    = (const float*)d_in[0];
    const float* Wqkv = (const float*)d_in[1];
    const float* Wout = (const float*)d_in[2];
    float* out = (float*)d_out;

    void* Oaddr = nullptr;
    cudaGetSymbolAddress(&Oaddr, g_O);

    cudaFuncSetAttribute(attn_kernel, cudaFuncAttributeMaxDynamicSharedMemorySize,
                         2 * BSZ * HDIM * (int)sizeof(float));

    // 1) QKV projection (tf32 tensor cores), scattered into [B,H,L,HD] Q/K/V
    mm_tf32<0><<<dim3(3 * DD / 128, MR / 128), 256>>>(x, Wqkv, nullptr, DD, 3 * DD);

    // 2) RoPE on Q and K (in place)
    rope_kernel<<<(2 * BB * NH * LL) / 8, 256>>>();

    // 3) Block-local causal attention -> g_O in [B,L,D] layout
    attn_kernel<<<BB * NH * NBLK, 256, 2 * BSZ * HDIM * (int)sizeof(float)>>>();

    // 4) Output projection (tf32 tensor cores)
    mm_tf32<1><<<dim3(DD / 128, MR / 128), 256>>>((const float*)Oaddr, Wout, out, DD, DD);
}

// round 3
// speedup vs baseline: 2.4286x; 1.0473x over previous
#include <cuda_runtime.h>
#include <math.h>

#define BB   2
#define LL   4096
#define DD   1024
#define NH   16
#define HDIM 64
#define BSZ  256
#define NBLK (LL / BSZ)     // 16
#define MR   (BB * LL)      // 8192

// Scratch (allocation-free, __device__ globals)
__device__ float g_Q[BB * NH * LL * HDIM];
__device__ float g_K[BB * NH * LL * HDIM];
__device__ float g_V[BB * NH * LL * HDIM];
__device__ float g_O[MR * DD];
// tf32-pre-rounded operands (so cp.async GEMM path needs no in-path cvt)
__device__ float g_Xt[MR * DD];
__device__ float g_Wqkvt[3 * DD * DD];
__device__ float g_Woutt[DD * DD];

__device__ __forceinline__ float f2tf32(float x) {
    asm("cvt.rna.tf32.f32 %0, %0;" : "+f"(x));
    return x;
}

__device__ __forceinline__ void mma_tf32(float* d, const unsigned* a, const unsigned* b) {
    asm volatile(
        "mma.sync.aligned.m16n8k8.row.col.f32.tf32.tf32.f32 "
        "{%0,%1,%2,%3}, {%4,%5,%6,%7}, {%8,%9}, {%0,%1,%2,%3};\n"
        : "+f"(d[0]), "+f"(d[1]), "+f"(d[2]), "+f"(d[3])
        : "r"(a[0]), "r"(a[1]), "r"(a[2]), "r"(a[3]),
          "r"(b[0]), "r"(b[1]));
}

__device__ __forceinline__ void cp16(float* smem_dst, const float* gmem_src) {
    unsigned s = (unsigned)__cvta_generic_to_shared(smem_dst);
    asm volatile("cp.async.cg.shared.global [%0], [%1], 16;\n" :: "r"(s), "l"(gmem_src));
}
__device__ __forceinline__ void cp_commit() {
    asm volatile("cp.async.commit_group;\n");
}
template <int N>
__device__ __forceinline__ void cp_wait() {
    asm volatile("cp.async.wait_group %0;\n" :: "n"(N));
}

// ---------------------------------------------------------------------------
// Pre-pass: round fp32 -> tf32-in-fp32 (RNA), float4 grid-stride.
// ---------------------------------------------------------------------------
__global__ void tf32_round_kernel(const float4* __restrict__ src,
                                  float4* __restrict__ dst, int n4)
{
    int i = blockIdx.x * blockDim.x + threadIdx.x;
    if (i < n4) {
        float4 v = src[i];
        dst[i] = make_float4(f2tf32(v.x), f2tf32(v.y), f2tf32(v.z), f2tf32(v.w));
    }
}

// ---------------------------------------------------------------------------
// tf32 tensor-core GEMM, cp.async double-buffered.
// C[M,N] = A[M,K] * B[N,K]^T, operands already tf32-rounded.
// 128x128 CTA tile, BK=32, 256 threads = 8 warps (2x4), warp tile 64x32.
// SMEM [row][k] stride 36, dynamic, 2 stages (72 KB). 2 CTAs/SM.
// MODE 0: scatter epilogue into g_Q/g_K/g_V; MODE 1: row-major C.
// ---------------------------------------------------------------------------
#define TSZ (128 * 36)

template <int MODE>
__global__ __launch_bounds__(256, 2)
void mm_tf32(const float* __restrict__ A, const float* __restrict__ Bm,
             float* __restrict__ C, int Kdim, int Ndim)
{
    extern __shared__ float smp[];
    // layout: A stage0 | A stage1 | B stage0 | B stage1
    const int m0 = blockIdx.y * 128;
    const int n0 = blockIdx.x * 128;
    const int t  = threadIdx.x;
    const int warp = t >> 5, lane = t & 31;
    const int wm = (warp >> 2) * 64;
    const int wn = (warp & 3) * 32;
    const int g = lane >> 2;
    const int q = lane & 3;

    // per-thread fill coordinates: 8 x 16B per stage (4 for A, 4 for B)
    // idx = t + u*256 (u=0..3): row = idx>>3 (0..127), kc = (idx&7)*4
    float acc[4][4][4];
#pragma unroll
    for (int i = 0; i < 4; i++)
#pragma unroll
        for (int j = 0; j < 4; j++)
#pragma unroll
            for (int r = 0; r < 4; r++) acc[i][j][r] = 0.f;

    const int KT = Kdim >> 5;

    auto prefetch = [&](int kt, int s) {
        float* As = smp + s * TSZ;
        float* Bs = smp + 2 * TSZ + s * TSZ;
        int k0 = kt << 5;
#pragma unroll
        for (int u = 0; u < 4; u++) {
            int idx = t + u * 256;
            int row = idx >> 3;
            int kc  = (idx & 7) << 2;
            cp16(As + row * 36 + kc, A + (size_t)(m0 + row) * Kdim + k0 + kc);
            cp16(Bs + row * 36 + kc, Bm + (size_t)(n0 + row) * Kdim + k0 + kc);
        }
    };

    prefetch(0, 0);
    cp_commit();

    for (int kt = 0; kt < KT; kt++) {
        int buf = kt & 1;
        if (kt + 1 < KT) {
            prefetch(kt + 1, buf ^ 1);
            cp_commit();
            cp_wait<1>();
        } else {
            cp_wait<0>();
        }
        __syncthreads();

        const float* As = smp + buf * TSZ;
        const float* Bs = smp + 2 * TSZ + buf * TSZ;

#pragma unroll
        for (int kk = 0; kk < 4; kk++) {
            const int k8 = kk * 8;
            unsigned af[4][4], bf[4][2];
#pragma unroll
            for (int mi = 0; mi < 4; mi++) {
                int m = wm + mi * 16 + g;
                af[mi][0] = __float_as_uint(As[m * 36 + k8 + q]);
                af[mi][1] = __float_as_uint(As[(m + 8) * 36 + k8 + q]);
                af[mi][2] = __float_as_uint(As[m * 36 + k8 + q + 4]);
                af[mi][3] = __float_as_uint(As[(m + 8) * 36 + k8 + q + 4]);
            }
#pragma unroll
            for (int ni = 0; ni < 4; ni++) {
                int n = wn + ni * 8 + g;
                bf[ni][0] = __float_as_uint(Bs[n * 36 + k8 + q]);
                bf[ni][1] = __float_as_uint(Bs[n * 36 + k8 + q + 4]);
            }
#pragma unroll
            for (int mi = 0; mi < 4; mi++)
#pragma unroll
                for (int ni = 0; ni < 4; ni++)
                    mma_tf32(acc[mi][ni], af[mi], bf[ni]);
        }
        __syncthreads();
    }

#pragma unroll
    for (int mi = 0; mi < 4; mi++) {
        int mA = m0 + wm + mi * 16 + g;
#pragma unroll
        for (int ni = 0; ni < 4; ni++) {
            int n = n0 + wn + ni * 8 + 2 * q;
            float2 v0 = make_float2(acc[mi][ni][0], acc[mi][ni][1]);
            float2 v1 = make_float2(acc[mi][ni][2], acc[mi][ni][3]);
            if (MODE == 1) {
                *(float2*)(C + (size_t)mA * Ndim + n) = v0;
                *(float2*)(C + (size_t)(mA + 8) * Ndim + n) = v1;
            } else {
                int sel = n >> 10;
                int h   = (n >> 6) & (NH - 1);
                int hd  = n & (HDIM - 1);
                float* dst = (sel == 0) ? g_Q : (sel == 1) ? g_K : g_V;
                int b0r = mA >> 12, l0 = mA & (LL - 1);
                int b1r = (mA + 8) >> 12, l1 = (mA + 8) & (LL - 1);
                *(float2*)(dst + ((size_t)(b0r * NH + h) * LL + l0) * HDIM + hd) = v0;
                *(float2*)(dst + ((size_t)(b1r * NH + h) * LL + l1) * HDIM + hd) = v1;
            }
        }
    }
}

// ---------------------------------------------------------------------------
// RoPE (in-place on g_Q and g_K). One warp per 64-float row.
// ---------------------------------------------------------------------------
__global__ void rope_kernel()
{
    const int nrows = BB * NH * LL;
    int gw   = (blockIdx.x * blockDim.x + threadIdx.x) >> 5;
    int lane = threadIdx.x & 31;

    float* buf = (gw < nrows) ? g_Q : g_K;
    int row = (gw < nrows) ? gw : gw - nrows;
    int l   = row & (LL - 1);

    float* p = buf + (size_t)row * HDIM;
    float2 xv = *(const float2*)(p + 2 * lane);

    float freq = expf(-(float)lane * (9.210340371976184f / 32.0f));
    float tt = (float)l * freq;
    float c = cosf(tt), s = sinf(tt);

    float o1 = xv.x * c - xv.y * s;
    float o2 = xv.y * c + xv.x * s;
    __syncwarp();
    p[lane]      = o1;
    p[lane + 32] = o2;
}

// ---------------------------------------------------------------------------
// Block-local causal attention. Epilogue now writes tf32-rounded O so the
// output projection can consume it through the cp.async path without cvt.
// ---------------------------------------------------------------------------
__global__ __launch_bounds__(256, 1)
void attn_kernel()
{
    extern __shared__ float sm[];
    float4* Ks4 = (float4*)sm;
    float4* Vs4 = (float4*)(sm + BSZ * HDIM);

    int cta = blockIdx.x;
    int nb  = cta & (NBLK - 1);
    int bh  = cta >> 4;
    int rowbase = bh * LL + nb * BSZ;

    const float4* Kg = (const float4*)(g_K + (size_t)rowbase * HDIM);
    const float4* Vg = (const float4*)(g_V + (size_t)rowbase * HDIM);
    for (int idx = threadIdx.x; idx < BSZ * HDIM / 4; idx += 256) {
        Ks4[idx] = Kg[idx];
        Vs4[idx] = Vg[idx];
    }

    const int i = threadIdx.x;
    float q[64];
    const float4* Qg = (const float4*)(g_Q + (size_t)(rowbase + i) * HDIM);
#pragma unroll
    for (int d = 0; d < 16; d++) ((float4*)q)[d] = Qg[d];
    __syncthreads();

    float mmax = -1e30f, lsum = 0.f;
    float acc[64];
#pragma unroll
    for (int d = 0; d < 64; d++) acc[d] = 0.f;

    const int jmax = i | 31;
    for (int j = 0; j <= jmax; j++) {
        float s = 0.f;
#pragma unroll
        for (int d = 0; d < 16; d++) {
            float4 k4 = Ks4[j * 16 + d];
            s += q[4*d+0] * k4.x + q[4*d+1] * k4.y
               + q[4*d+2] * k4.z + q[4*d+3] * k4.w;
        }
        s *= 0.125f;
        if (j <= i) {
            if (s <= mmax) {
                float p = __expf(s - mmax);
                lsum += p;
#pragma unroll
                for (int d = 0; d < 16; d++) {
                    float4 v4 = Vs4[j * 16 + d];
                    acc[4*d+0] += p * v4.x;
                    acc[4*d+1] += p * v4.y;
                    acc[4*d+2] += p * v4.z;
                    acc[4*d+3] += p * v4.w;
                }
            } else {
                float cc = __expf(mmax - s);
                mmax = s;
                lsum = lsum * cc + 1.f;
#pragma unroll
                for (int d = 0; d < 16; d++) {
                    float4 v4 = Vs4[j * 16 + d];
                    acc[4*d+0] = acc[4*d+0] * cc + v4.x;
                    acc[4*d+1] = acc[4*d+1] * cc + v4.y;
                    acc[4*d+2] = acc[4*d+2] * cc + v4.z;
                    acc[4*d+3] = acc[4*d+3] * cc + v4.w;
                }
            }
        }
    }

    float inv = 1.f / lsum;
    int b = bh >> 4;
    int h = bh & (NH - 1);
    float* Og = g_O + (size_t)(b * LL + nb * BSZ + i) * DD + h * HDIM;
#pragma unroll
    for (int d = 0; d < 16; d++) {
        float4 o = make_float4(f2tf32(acc[4*d+0] * inv), f2tf32(acc[4*d+1] * inv),
                               f2tf32(acc[4*d+2] * inv), f2tf32(acc[4*d+3] * inv));
        ((float4*)Og)[d] = o;
    }
}

// ---------------------------------------------------------------------------
extern "C" void kernel_launch(void* const* d_in, const int* in_sizes, int n_in,
                              void* d_out, int out_size)
{
    const float* x    = (const float*)d_in[0];
    const float* Wqkv = (const float*)d_in[1];
    const float* Wout = (const float*)d_in[2];
    float* out = (float*)d_out;

    void *Oaddr = nullptr, *Xt = nullptr, *Wqt = nullptr, *Wot = nullptr;
    cudaGetSymbolAddress(&Oaddr, g_O);
    cudaGetSymbolAddress(&Xt, g_Xt);
    cudaGetSymbolAddress(&Wqt, g_Wqkvt);
    cudaGetSymbolAddress(&Wot, g_Woutt);

    const int GEMM_SMEM = 4 * TSZ * (int)sizeof(float);   // 73728 B
    cudaFuncSetAttribute(mm_tf32<0>, cudaFuncAttributeMaxDynamicSharedMemorySize, GEMM_SMEM);
    cudaFuncSetAttribute(mm_tf32<1>, cudaFuncAttributeMaxDynamicSharedMemorySize, GEMM_SMEM);
    cudaFuncSetAttribute(attn_kernel, cudaFuncAttributeMaxDynamicSharedMemorySize,
                         2 * BSZ * HDIM * (int)sizeof(float));

    // 0) tf32 pre-round of x, Wqkv, Wout
    {
        int n4x = MR * DD / 4, n4q = 3 * DD * DD / 4, n4o = DD * DD / 4;
        tf32_round_kernel<<<(n4x + 255) / 256, 256>>>((const float4*)x, (float4*)Xt, n4x);
        tf32_round_kernel<<<(n4q + 255) / 256, 256>>>((const float4*)Wqkv, (float4*)Wqt, n4q);
        tf32_round_kernel<<<(n4o + 255) / 256, 256>>>((const float4*)Wout, (float4*)Wot, n4o);
    }

    // 1) QKV projection, scattered into [B,H,L,HD] Q/K/V
    mm_tf32<0><<<dim3(3 * DD / 128, MR / 128), 256, GEMM_SMEM>>>(
        (const float*)Xt, (const float*)Wqt, nullptr, DD, 3 * DD);

    // 2) RoPE on Q and K (in place)
    rope_kernel<<<(2 * BB * NH * LL) / 8, 256>>>();

    // 3) Block-local causal attention -> g_O (tf32-rounded) in [B,L,D] layout
    attn_kernel<<<BB * NH * NBLK, 256, 2 * BSZ * HDIM * (int)sizeof(float)>>>();

    // 4) Output projection
    mm_tf32<1><<<dim3(DD / 128, MR / 128), 256, GEMM_SMEM>>>(
        (const float*)Oaddr, (const float*)Wot, out, DD, DD);
}